// round 15
// baseline (speedup 1.0000x reference)
#include <cuda_runtime.h>
#include <cuda_fp16.h>
#include <cstdint>

#define EMBED 1024
#define NHEAD 16
#define HDIM  64
#define BATCH 4
#define SEQ   2048
#define MTOT  (BATCH*SEQ)      /* 8192 */
#define QKVF  (3*EMBED)        /* 3072 */

// fp16 scratch (device globals: allocation-free per harness rules)
__device__ __half g_hx[(size_t)MTOT * EMBED];     // x in fp16
__device__ __half g_hw_qkv[(size_t)QKVF * EMBED]; // qkv_w fp16
__device__ __half g_hw_out[(size_t)EMBED * EMBED];// out_w fp16
__device__ __half g_hqkv[(size_t)MTOT * QKVF];    // qkv activations fp16
__device__ __half g_hatt[(size_t)MTOT * EMBED];   // attention output fp16

__device__ __forceinline__ uint32_t f2h2(float a, float b) {
  __half2 h = __floats2half2_rn(a, b);
  return *(uint32_t*)&h;
}

__device__ __forceinline__ void mma_f16(float c[4], const uint4& a, const uint2& b) {
  asm volatile(
    "mma.sync.aligned.m16n8k16.row.col.f32.f16.f16.f32 "
    "{%0,%1,%2,%3}, {%4,%5,%6,%7}, {%8,%9}, {%0,%1,%2,%3};\n"
    : "+f"(c[0]), "+f"(c[1]), "+f"(c[2]), "+f"(c[3])
    : "r"(a.x), "r"(a.y), "r"(a.z), "r"(a.w), "r"(b.x), "r"(b.y));
}

__device__ __forceinline__ uint32_t smem_u32(const void* p) {
  uint32_t a;
  asm("{ .reg .u64 t; cvta.to.shared.u64 t, %1; cvt.u32.u64 %0, t; }"
      : "=r"(a) : "l"(p));
  return a;
}

__device__ __forceinline__ void ldsm4(uint4& d, uint32_t addr) {
  asm volatile("ldmatrix.sync.aligned.m8n8.x4.shared.b16 {%0,%1,%2,%3}, [%4];"
               : "=r"(d.x), "=r"(d.y), "=r"(d.z), "=r"(d.w) : "r"(addr));
}

__device__ __forceinline__ void ldsm4t(uint4& d, uint32_t addr) {
  asm volatile("ldmatrix.sync.aligned.m8n8.x4.trans.shared.b16 {%0,%1,%2,%3}, [%4];"
               : "=r"(d.x), "=r"(d.y), "=r"(d.z), "=r"(d.w) : "r"(addr));
}

__device__ __forceinline__ void cp16(uint32_t dst, const void* src) {
  asm volatile("cp.async.ca.shared.global [%0], [%1], 16;"
               :: "r"(dst), "l"(src) : "memory");
}
__device__ __forceinline__ void cpcommit() {
  asm volatile("cp.async.commit_group;" ::: "memory");
}
template<int N> __device__ __forceinline__ void cpwait() {
  asm volatile("cp.async.wait_group %0;" :: "n"(N) : "memory");
}

// ---------------------------------------------------------------------------
// fp32 -> fp16 conversion pass (vectorized)
// ---------------------------------------------------------------------------
__global__ void f2h_kernel(const float4* __restrict__ src, uint2* __restrict__ dst,
                           int n4)
{
  int i = blockIdx.x * blockDim.x + threadIdx.x;
  if (i < n4) {
    float4 v = src[i];
    dst[i] = make_uint2(f2h2(v.x, v.y), f2h2(v.z, v.w));
  }
}

// ===========================================================================
// FP16 GEMM (fp32 accum): C[M,N] = A[M,K] @ B[N,K]^T + bias[N]
// CTA 128x128x32, 128 threads = 4 warps of 64x64 warp tiles (2m x 2n).
// 3-stage cp.async ring (61.4KB smem) + __launch_bounds__(128,3):
// 3 CTAs/SM -> 12 warps/SM (3 per SMSP) to feed the HMMA pipe.
// Rows padded to 80B (ldsm bank-quads 5r mod 8 -> conflict-free).
// ===========================================================================
#define GROWB 80
#define GATILE_B (128 * GROWB)          /* 10240 B */
#define GSTAGE_B (2 * GATILE_B)         /* 20480 B */
#define GSTAGES 3
#define GSMEM_BYTES (GSTAGES * GSTAGE_B)   /* 61440 B */

template<bool OUTH>
__global__ __launch_bounds__(128, 3) void gemm_h(
    const __half* __restrict__ A, const __half* __restrict__ Bm,
    const float* __restrict__ bias, void* __restrict__ Cv,
    int M, int N, int K)
{
  extern __shared__ char gsm[];
  const uint32_t sb = smem_u32(gsm);

  const int tid  = threadIdx.x;
  const int lane = tid & 31;
  const int wid  = tid >> 5;
  const int wm   = wid & 1;
  const int wn   = wid >> 1;
  const int m0   = blockIdx.y * 128;
  const int n0   = blockIdx.x * 128;
  const int r0   = lane >> 2;
  const int tq   = lane & 3;

  const uint32_t a_lane = (uint32_t)((lane & 7) * GROWB +
                          ((lane >> 3) & 1) * 8 * GROWB + (lane >> 4) * 16);
  const uint32_t b_lane = (uint32_t)((lane & 7) * GROWB + (lane >> 3) * 16);

  float acc[4][8][4];
  #pragma unroll
  for (int i = 0; i < 4; i++)
    #pragma unroll
    for (int j = 0; j < 8; j++)
      #pragma unroll
      for (int r = 0; r < 4; r++) acc[i][j][r] = 0.0f;

  auto fill = [&](int s, int k0) {
    const uint32_t base = sb + (uint32_t)s * GSTAGE_B;
    #pragma unroll
    for (int i = 0; i < 4; i++) {
      int idx = tid + 128 * i;
      int row = idx >> 2, ch = idx & 3;
      uint32_t off = (uint32_t)(row * GROWB + ch * 16);
      cp16(base + off,            A  + (size_t)(m0 + row) * K + k0 + ch * 8);
      cp16(base + GATILE_B + off, Bm + (size_t)(n0 + row) * K + k0 + ch * 8);
    }
    cpcommit();
  };

  auto compute = [&](int s) {
    const uint32_t As = sb + (uint32_t)s * GSTAGE_B + (uint32_t)(wm * 64 * GROWB);
    const uint32_t Bs = sb + (uint32_t)s * GSTAGE_B + GATILE_B +
                        (uint32_t)(wn * 64 * GROWB);
    uint4 af[2][4];
    #pragma unroll
    for (int mf = 0; mf < 4; mf++) {
      uint4 t0, t1;
      ldsm4(t0, As + a_lane + (uint32_t)(mf * 16 * GROWB));
      ldsm4(t1, As + a_lane + (uint32_t)(mf * 16 * GROWB + 32));
      af[0][mf] = t0;
      af[1][mf] = t1;
    }
    #pragma unroll
    for (int nt = 0; nt < 8; nt++) {
      uint4 braw;
      ldsm4(braw, Bs + b_lane + (uint32_t)(nt * 8 * GROWB));
      uint2 bf0 = make_uint2(braw.x, braw.y);
      uint2 bf1 = make_uint2(braw.z, braw.w);
      #pragma unroll
      for (int mf = 0; mf < 4; mf++) {
        mma_f16(acc[mf][nt], af[0][mf], bf0);
        mma_f16(acc[mf][nt], af[1][mf], bf1);
      }
    }
  };

  const int nk = K >> 5;   // >= 32
  fill(0, 0);
  fill(1, 32);

  int st = 0;                       // stage of iteration t
  for (int t = 0; t < nk; t++) {
    cpwait<1>();
    __syncthreads();
    if (t + 2 < nk) {
      int sf = st + 2; if (sf >= GSTAGES) sf -= GSTAGES;
      fill(sf, (t + 2) << 5);
    }
    compute(st);
    if (++st == GSTAGES) st = 0;
  }

  const int gn_base = n0 + wn * 64 + (tq << 1);
  #pragma unroll
  for (int mf = 0; mf < 4; mf++) {
    int gm = m0 + wm * 64 + mf * 16 + r0;
    #pragma unroll
    for (int nt = 0; nt < 8; nt++) {
      int gn = gn_base + nt * 8;
      float b0 = bias[gn], b1 = bias[gn + 1];
      float c00 = acc[mf][nt][0] + b0, c01 = acc[mf][nt][1] + b1;
      float c10 = acc[mf][nt][2] + b0, c11 = acc[mf][nt][3] + b1;
      if (OUTH) {
        __half* C = (__half*)Cv;
        *(uint32_t*)(C + (size_t)gm * N + gn)       = f2h2(c00, c01);
        *(uint32_t*)(C + (size_t)(gm + 8) * N + gn) = f2h2(c10, c11);
      } else {
        float* C = (float*)Cv;
        *(float2*)(C + (size_t)gm * N + gn)       = make_float2(c00, c01);
        *(float2*)(C + (size_t)(gm + 8) * N + gn) = make_float2(c10, c11);
      }
    }
  }
}

// ===========================================================================
// Flash attention, FP16 mma m16n8k16, register-resident P@V, hoisted Q frags.
// LPT scheduling: bx reversed so heavy (large-kv-range) blocks launch first.
// 128 threads = 4 warps of 32q x 64k. cp.async double-buffered K/V tiles.
// ===========================================================================
#define FQF_B  0                       /* 16384 B */
#define FKT0_B 16384
#define FVS0_B (16384 + 9216)
#define FKT1_B (16384 + 2*9216)
#define FVS1_B (16384 + 3*9216)
#define FTOT_B (16384 + 4*9216)        /* 53248 B */

__global__ __launch_bounds__(128) void flash_h(
    const __half* __restrict__ qkv, __half* __restrict__ out)
{
  extern __shared__ char fsm[];
  uint32_t* QF = (uint32_t*)(fsm + FQF_B);
  const uint32_t sbase = smem_u32(fsm);
  const uint32_t KtB[2] = { sbase + FKT0_B, sbase + FKT1_B };
  const uint32_t VsB[2] = { sbase + FVS0_B, sbase + FVS1_B };

  const int tid  = threadIdx.x;
  const int lane = tid & 31;
  const int w    = tid >> 5;
  const int bx   = (int)gridDim.x - 1 - (int)blockIdx.x;   // LPT: heavy first
  const int bh   = blockIdx.y;
  const int b    = bh >> 4;
  const int h    = bh & 15;
  const int q0   = bx * 128;

  const __half* qb = qkv + ((size_t)b * SEQ + q0) * QKVF + h * HDIM;
  const __half* kb = qkv + ((size_t)b * SEQ) * QKVF + EMBED + h * HDIM;
  const __half* vb = kb + EMBED;

  auto fillkv = [&](int buf, int k0) {
    #pragma unroll
    for (int i = 0; i < 4; i++) {
      int idx = tid + 128 * i;
      int row = idx >> 3, ch = idx & 7;
      uint32_t off = (uint32_t)(row * 144 + ch * 16);
      cp16(KtB[buf] + off, kb + (size_t)(k0 + row) * QKVF + ch * 8);
      cp16(VsB[buf] + off, vb + (size_t)(k0 + row) * QKVF + ch * 8);
    }
    cpcommit();
  };
  fillkv(0, 0);

  // ---- Q scatter into fp16 fragment layout (once), scaled by 1/8 ----
  {
    const __half2 sc = __floats2half2_rn(0.125f, 0.125f);
    for (int e = tid; e < 128 * 8; e += 128) {
      int r = e >> 3, c8 = (e & 7) << 3;
      uint4 qv = *(const uint4*)(qb + (size_t)r * QKVF + c8);
      uint32_t wds[4] = { qv.x, qv.y, qv.z, qv.w };
      int wq = r >> 5, m = (r >> 4) & 1, rr = r & 15;
      int frag = (wq * 2 + m) * 4 + (c8 >> 4);
      int rg = (rr >> 3) | (((c8 & 15) >> 3) << 1);
      #pragma unroll
      for (int j = 0; j < 4; j++) {
        __half2 hv = __hmul2(*(__half2*)&wds[j], sc);
        QF[frag * 128 + ((rr & 7) * 4 + j) * 4 + rg] = *(uint32_t*)&hv;
      }
    }
  }
  __syncthreads();   // QF complete before hoisted fragment loads

  // ---- Q a-frags: load ONCE (hoisted out of kv loop) ----
  uint4 qa[2][4];
  #pragma unroll
  for (int m = 0; m < 2; m++)
    #pragma unroll
    for (int ks = 0; ks < 4; ks++)
      qa[m][ks] = *(const uint4*)&QF[(((w * 2 + m) * 4 + ks) * 128) + lane * 4];

  const int r0 = lane >> 2;
  const int tq = lane & 3;
  const int qmin = q0 + w * 32;
  const int qmax = qmin + 31;
  const int qg[2] = { qmin + r0, qmin + 16 + r0 };

  const uint32_t kb_lane = (uint32_t)((lane & 7) * 144 + (lane >> 3) * 16);
  const int vm = lane >> 3;
  const uint32_t vb_lane = (uint32_t)(((vm & 1) * 8 + (lane & 7)) * 144 +
                                      (vm >> 1) * 16);

  float mrow[2][2], lrow[2][2];
  #pragma unroll
  for (int m = 0; m < 2; m++) {
    mrow[m][0] = mrow[m][1] = -1e30f;
    lrow[m][0] = lrow[m][1] = 0.0f;
  }
  float o[2][8][4];
  #pragma unroll
  for (int m = 0; m < 2; m++)
    #pragma unroll
    for (int nt = 0; nt < 8; nt++)
      #pragma unroll
      for (int j = 0; j < 4; j++) o[m][nt][j] = 0.0f;

  const int nkv = 2 * bx + 2;
  for (int kv = 0; kv < nkv; kv++) {
    const int k0 = kv * 64;
    const int buf = kv & 1;
    __syncthreads();
    if (kv + 1 < nkv) fillkv(buf ^ 1, k0 + 64);
    if (kv + 1 < nkv) cpwait<1>(); else cpwait<0>();
    __syncthreads();

    if (k0 > qmax) continue;

    // ---- S = Q @ K^T ----
    float s[2][8][4];
    #pragma unroll
    for (int m = 0; m < 2; m++)
      #pragma unroll
      for (int nt = 0; nt < 8; nt++)
        s[m][nt][0] = s[m][nt][1] = s[m][nt][2] = s[m][nt][3] = 0.0f;

    #pragma unroll
    for (int nt = 0; nt < 8; nt++) {
      uint4 kr0, kr1;
      ldsm4(kr0, KtB[buf] + kb_lane + (uint32_t)(nt * 8 * 144));
      ldsm4(kr1, KtB[buf] + kb_lane + (uint32_t)(nt * 8 * 144 + 64));
      uint2 bk[4] = { make_uint2(kr0.x, kr0.y), make_uint2(kr0.z, kr0.w),
                      make_uint2(kr1.x, kr1.y), make_uint2(kr1.z, kr1.w) };
      #pragma unroll
      for (int ks = 0; ks < 4; ks++) {
        mma_f16(s[0][nt], qa[0][ks], bk[ks]);
        mma_f16(s[1][nt], qa[1][ks], bk[ks]);
      }
    }

    // ---- causal mask ----
    if (k0 + 63 > qmin) {
      #pragma unroll
      for (int m = 0; m < 2; m++) {
        #pragma unroll
        for (int nt = 0; nt < 8; nt++) {
          int c0 = k0 + 8 * nt + 2 * tq;
          int c1 = c0 + 1;
          if (c0 > qg[m])     s[m][nt][0] = -1e30f;
          if (c1 > qg[m])     s[m][nt][1] = -1e30f;
          if (c0 > qg[m] + 8) s[m][nt][2] = -1e30f;
          if (c1 > qg[m] + 8) s[m][nt][3] = -1e30f;
        }
      }
    }

    // ---- online softmax; P stays in registers (overwrites s) ----
    #pragma unroll
    for (int m = 0; m < 2; m++) {
      float mx0 = -1e30f, mx1 = -1e30f;
      #pragma unroll
      for (int nt = 0; nt < 8; nt++) {
        mx0 = fmaxf(mx0, fmaxf(s[m][nt][0], s[m][nt][1]));
        mx1 = fmaxf(mx1, fmaxf(s[m][nt][2], s[m][nt][3]));
      }
      mx0 = fmaxf(mx0, __shfl_xor_sync(0xffffffffu, mx0, 1));
      mx0 = fmaxf(mx0, __shfl_xor_sync(0xffffffffu, mx0, 2));
      mx1 = fmaxf(mx1, __shfl_xor_sync(0xffffffffu, mx1, 1));
      mx1 = fmaxf(mx1, __shfl_xor_sync(0xffffffffu, mx1, 2));

      float mn0 = fmaxf(mrow[m][0], mx0), mn1 = fmaxf(mrow[m][1], mx1);
      float a0 = __expf(mrow[m][0] - mn0), a1 = __expf(mrow[m][1] - mn1);
      mrow[m][0] = mn0; mrow[m][1] = mn1;

      float rs0 = 0.0f, rs1 = 0.0f;
      #pragma unroll
      for (int nt = 0; nt < 8; nt++) {
        s[m][nt][0] = __expf(s[m][nt][0] - mn0);
        s[m][nt][1] = __expf(s[m][nt][1] - mn0);
        s[m][nt][2] = __expf(s[m][nt][2] - mn1);
        s[m][nt][3] = __expf(s[m][nt][3] - mn1);
        rs0 += s[m][nt][0] + s[m][nt][1];
        rs1 += s[m][nt][2] + s[m][nt][3];
      }
      rs0 += __shfl_xor_sync(0xffffffffu, rs0, 1);
      rs0 += __shfl_xor_sync(0xffffffffu, rs0, 2);
      rs1 += __shfl_xor_sync(0xffffffffu, rs1, 1);
      rs1 += __shfl_xor_sync(0xffffffffu, rs1, 2);
      lrow[m][0] = lrow[m][0] * a0 + rs0;
      lrow[m][1] = lrow[m][1] * a1 + rs1;
      #pragma unroll
      for (int nt = 0; nt < 8; nt++) {
        o[m][nt][0] *= a0; o[m][nt][1] *= a0;
        o[m][nt][2] *= a1; o[m][nt][3] *= a1;
      }
    }

    // ---- O += P @ V : P a-frags built directly from S c-frags ----
    #pragma unroll
    for (int ks = 0; ks < 4; ks++) {
      uint4 pa0 = make_uint4(f2h2(s[0][2*ks][0],   s[0][2*ks][1]),
                             f2h2(s[0][2*ks][2],   s[0][2*ks][3]),
                             f2h2(s[0][2*ks+1][0], s[0][2*ks+1][1]),
                             f2h2(s[0][2*ks+1][2], s[0][2*ks+1][3]));
      uint4 pa1 = make_uint4(f2h2(s[1][2*ks][0],   s[1][2*ks][1]),
                             f2h2(s[1][2*ks][2],   s[1][2*ks][3]),
                             f2h2(s[1][2*ks+1][0], s[1][2*ks+1][1]),
                             f2h2(s[1][2*ks+1][2], s[1][2*ks+1][3]));
      #pragma unroll
      for (int j = 0; j < 4; j++) {
        uint4 vr;
        ldsm4t(vr, VsB[buf] + vb_lane + (uint32_t)(16 * ks * 144 + j * 32));
        uint2 bv0 = make_uint2(vr.x, vr.y);
        uint2 bv1 = make_uint2(vr.z, vr.w);
        mma_f16(o[0][2*j],     pa0, bv0);
        mma_f16(o[0][2*j + 1], pa0, bv1);
        mma_f16(o[1][2*j],     pa1, bv0);
        mma_f16(o[1][2*j + 1], pa1, bv1);
      }
    }
  }

  // ---- epilogue: normalize, write fp16 [B,T,C] ----
  #pragma unroll
  for (int m = 0; m < 2; m++) {
    float inv0 = 1.0f / lrow[m][0], inv1 = 1.0f / lrow[m][1];
    __half* orow0 = out + ((size_t)b * SEQ + q0 + w * 32 + m * 16 + r0) * EMBED + h * HDIM;
    __half* orow1 = orow0 + (size_t)8 * EMBED;
    #pragma unroll
    for (int nt = 0; nt < 8; nt++) {
      *(uint32_t*)(orow0 + 8 * nt + 2 * tq) =
          f2h2(o[m][nt][0] * inv0, o[m][nt][1] * inv0);
      *(uint32_t*)(orow1 + 8 * nt + 2 * tq) =
          f2h2(o[m][nt][2] * inv1, o[m][nt][3] * inv1);
    }
  }
}

// ---------------------------------------------------------------------------
extern "C" void kernel_launch(void* const* d_in, const int* in_sizes, int n_in,
                              void* d_out, int out_size)
{
  (void)in_sizes; (void)n_in; (void)out_size;
  const float* x     = (const float*)d_in[0];
  const float* qkv_w = (const float*)d_in[1];
  const float* qkv_b = (const float*)d_in[2];
  const float* out_w = (const float*)d_in[3];
  const float* out_b = (const float*)d_in[4];
  float* y = (float*)d_out;

  __half *hx, *hwq, *hwo, *hqkv, *hatt;
  cudaGetSymbolAddress((void**)&hx,   g_hx);
  cudaGetSymbolAddress((void**)&hwq,  g_hw_qkv);
  cudaGetSymbolAddress((void**)&hwo,  g_hw_out);
  cudaGetSymbolAddress((void**)&hqkv, g_hqkv);
  cudaGetSymbolAddress((void**)&hatt, g_hatt);

  cudaFuncSetAttribute(gemm_h<true>,
                       cudaFuncAttributeMaxDynamicSharedMemorySize, GSMEM_BYTES);
  cudaFuncSetAttribute(gemm_h<false>,
                       cudaFuncAttributeMaxDynamicSharedMemorySize, GSMEM_BYTES);
  cudaFuncSetAttribute(flash_h,
                       cudaFuncAttributeMaxDynamicSharedMemorySize, FTOT_B);

  // 0) fp32 -> fp16 conversions
  {
    int n4x = MTOT * EMBED / 4;
    f2h_kernel<<<(n4x + 255) / 256, 256>>>((const float4*)x, (uint2*)hx, n4x);
    int n4q = QKVF * EMBED / 4;
    f2h_kernel<<<(n4q + 255) / 256, 256>>>((const float4*)qkv_w, (uint2*)hwq, n4q);
    int n4o = EMBED * EMBED / 4;
    f2h_kernel<<<(n4o + 255) / 256, 256>>>((const float4*)out_w, (uint2*)hwo, n4o);
  }

  // 1) QKV projection (fp16 in, fp16 out)
  gemm_h<true><<<dim3(QKVF/128, MTOT/128), 128, GSMEM_BYTES>>>(
      hx, hwq, qkv_b, hqkv, MTOT, QKVF, EMBED);
  // 2) Causal flash attention (fp16, reg-resident P@V, LPT block order)
  flash_h<<<dim3(SEQ/128, BATCH*NHEAD), 128, FTOT_B>>>(hqkv, hatt);
  // 3) Output projection (fp16 in, fp32 out)
  gemm_h<false><<<dim3(EMBED/128, MTOT/128), 128, GSMEM_BYTES>>>(
      hatt, hwo, out_b, y, MTOT, EMBED, EMBED);
}

// round 16
// speedup vs baseline: 1.1794x; 1.1794x over previous
#include <cuda_runtime.h>
#include <cuda_fp16.h>
#include <cstdint>

#define EMBED 1024
#define NHEAD 16
#define HDIM  64
#define BATCH 4
#define SEQ   2048
#define MTOT  (BATCH*SEQ)      /* 8192 */
#define QKVF  (3*EMBED)        /* 3072 */

// fp16 scratch (device globals: allocation-free per harness rules)
__device__ __half g_hx[(size_t)MTOT * EMBED];     // x in fp16
__device__ __half g_hw_qkv[(size_t)QKVF * EMBED]; // qkv_w fp16
__device__ __half g_hw_out[(size_t)EMBED * EMBED];// out_w fp16
__device__ __half g_hqkv[(size_t)MTOT * QKVF];    // qkv activations fp16
__device__ __half g_hatt[(size_t)MTOT * EMBED];   // attention output fp16

__device__ __forceinline__ uint32_t f2h2(float a, float b) {
  __half2 h = __floats2half2_rn(a, b);
  return *(uint32_t*)&h;
}

__device__ __forceinline__ void mma_f16(float c[4], const uint4& a, const uint2& b) {
  asm volatile(
    "mma.sync.aligned.m16n8k16.row.col.f32.f16.f16.f32 "
    "{%0,%1,%2,%3}, {%4,%5,%6,%7}, {%8,%9}, {%0,%1,%2,%3};\n"
    : "+f"(c[0]), "+f"(c[1]), "+f"(c[2]), "+f"(c[3])
    : "r"(a.x), "r"(a.y), "r"(a.z), "r"(a.w), "r"(b.x), "r"(b.y));
}

__device__ __forceinline__ uint32_t smem_u32(const void* p) {
  uint32_t a;
  asm("{ .reg .u64 t; cvta.to.shared.u64 t, %1; cvt.u32.u64 %0, t; }"
      : "=r"(a) : "l"(p));
  return a;
}

__device__ __forceinline__ void ldsm4(uint4& d, uint32_t addr) {
  asm volatile("ldmatrix.sync.aligned.m8n8.x4.shared.b16 {%0,%1,%2,%3}, [%4];"
               : "=r"(d.x), "=r"(d.y), "=r"(d.z), "=r"(d.w) : "r"(addr));
}

__device__ __forceinline__ void ldsm4t(uint4& d, uint32_t addr) {
  asm volatile("ldmatrix.sync.aligned.m8n8.x4.trans.shared.b16 {%0,%1,%2,%3}, [%4];"
               : "=r"(d.x), "=r"(d.y), "=r"(d.z), "=r"(d.w) : "r"(addr));
}

__device__ __forceinline__ void cp16(uint32_t dst, const void* src) {
  asm volatile("cp.async.ca.shared.global [%0], [%1], 16;"
               :: "r"(dst), "l"(src) : "memory");
}
__device__ __forceinline__ void cpcommit() {
  asm volatile("cp.async.commit_group;" ::: "memory");
}
template<int N> __device__ __forceinline__ void cpwait() {
  asm volatile("cp.async.wait_group %0;" :: "n"(N) : "memory");
}

// ---------------------------------------------------------------------------
// fp32 -> fp16 conversion pass (vectorized)
// ---------------------------------------------------------------------------
__global__ void f2h_kernel(const float4* __restrict__ src, uint2* __restrict__ dst,
                           int n4)
{
  int i = blockIdx.x * blockDim.x + threadIdx.x;
  if (i < n4) {
    float4 v = src[i];
    dst[i] = make_uint2(f2h2(v.x, v.y), f2h2(v.z, v.w));
  }
}

// ===========================================================================
// FP16 GEMM (fp32 accum): C[M,N] = A[M,K] @ B[N,K]^T + bias[N]
// CTA 128x128x32, 128 threads = 4 warps of 64x64 warp tiles (2m x 2n).
// 4-stage cp.async ring, __launch_bounds__(128,2) — R14 config (210 regs,
// no spills; proven 162us). Rows padded to 80B (conflict-free ldsm).
// ===========================================================================
#define GROWB 80
#define GATILE_B (128 * GROWB)          /* 10240 B */
#define GSTAGE_B (2 * GATILE_B)         /* 20480 B */
#define GSMEM_BYTES (4 * GSTAGE_B)      /* 81920 B */

template<bool OUTH>
__global__ __launch_bounds__(128, 2) void gemm_h(
    const __half* __restrict__ A, const __half* __restrict__ Bm,
    const float* __restrict__ bias, void* __restrict__ Cv,
    int M, int N, int K)
{
  extern __shared__ char gsm[];
  const uint32_t sb = smem_u32(gsm);

  const int tid  = threadIdx.x;
  const int lane = tid & 31;
  const int wid  = tid >> 5;
  const int wm   = wid & 1;
  const int wn   = wid >> 1;
  const int m0   = blockIdx.y * 128;
  const int n0   = blockIdx.x * 128;
  const int r0   = lane >> 2;
  const int tq   = lane & 3;

  const uint32_t a_lane = (uint32_t)((lane & 7) * GROWB +
                          ((lane >> 3) & 1) * 8 * GROWB + (lane >> 4) * 16);
  const uint32_t b_lane = (uint32_t)((lane & 7) * GROWB + (lane >> 3) * 16);

  float acc[4][8][4];
  #pragma unroll
  for (int i = 0; i < 4; i++)
    #pragma unroll
    for (int j = 0; j < 8; j++)
      #pragma unroll
      for (int r = 0; r < 4; r++) acc[i][j][r] = 0.0f;

  auto fill = [&](int s, int k0) {
    const uint32_t base = sb + (uint32_t)s * GSTAGE_B;
    #pragma unroll
    for (int i = 0; i < 4; i++) {
      int idx = tid + 128 * i;
      int row = idx >> 2, ch = idx & 3;
      uint32_t off = (uint32_t)(row * GROWB + ch * 16);
      cp16(base + off,            A  + (size_t)(m0 + row) * K + k0 + ch * 8);
      cp16(base + GATILE_B + off, Bm + (size_t)(n0 + row) * K + k0 + ch * 8);
    }
    cpcommit();
  };

  auto compute = [&](int s) {
    const uint32_t As = sb + (uint32_t)s * GSTAGE_B + (uint32_t)(wm * 64 * GROWB);
    const uint32_t Bs = sb + (uint32_t)s * GSTAGE_B + GATILE_B +
                        (uint32_t)(wn * 64 * GROWB);
    uint4 af[2][4];
    #pragma unroll
    for (int mf = 0; mf < 4; mf++) {
      uint4 t0, t1;
      ldsm4(t0, As + a_lane + (uint32_t)(mf * 16 * GROWB));
      ldsm4(t1, As + a_lane + (uint32_t)(mf * 16 * GROWB + 32));
      af[0][mf] = t0;
      af[1][mf] = t1;
    }
    #pragma unroll
    for (int nt = 0; nt < 8; nt++) {
      uint4 braw;
      ldsm4(braw, Bs + b_lane + (uint32_t)(nt * 8 * GROWB));
      uint2 bf0 = make_uint2(braw.x, braw.y);
      uint2 bf1 = make_uint2(braw.z, braw.w);
      #pragma unroll
      for (int mf = 0; mf < 4; mf++) {
        mma_f16(acc[mf][nt], af[0][mf], bf0);
        mma_f16(acc[mf][nt], af[1][mf], bf1);
      }
    }
  };

  const int nk = K >> 5;
  fill(0, 0);
  fill(1, 32);
  fill(2, 64);

  for (int t = 0; t < nk; t++) {
    cpwait<2>();
    __syncthreads();
    if (t + 3 < nk) fill((t + 3) & 3, (t + 3) << 5);
    compute(t & 3);
  }

  const int gn_base = n0 + wn * 64 + (tq << 1);
  #pragma unroll
  for (int mf = 0; mf < 4; mf++) {
    int gm = m0 + wm * 64 + mf * 16 + r0;
    #pragma unroll
    for (int nt = 0; nt < 8; nt++) {
      int gn = gn_base + nt * 8;
      float b0 = bias[gn], b1 = bias[gn + 1];
      float c00 = acc[mf][nt][0] + b0, c01 = acc[mf][nt][1] + b1;
      float c10 = acc[mf][nt][2] + b0, c11 = acc[mf][nt][3] + b1;
      if (OUTH) {
        __half* C = (__half*)Cv;
        *(uint32_t*)(C + (size_t)gm * N + gn)       = f2h2(c00, c01);
        *(uint32_t*)(C + (size_t)(gm + 8) * N + gn) = f2h2(c10, c11);
      } else {
        float* C = (float*)Cv;
        *(float2*)(C + (size_t)gm * N + gn)       = make_float2(c00, c01);
        *(float2*)(C + (size_t)(gm + 8) * N + gn) = make_float2(c10, c11);
      }
    }
  }
}

// ===========================================================================
// Flash attention, FP16 mma m16n8k16, register-resident P@V, hoisted Q frags,
// LPT block order, and SINGLE __syncthreads per kv iteration:
// fill(kv+1) is issued right after the barrier that orders all warps past
// compute(kv-1) (the last reader of the buffer being overwritten), so the
// second barrier of the old loop is redundant. Same overlap depth.
// ===========================================================================
#define FQF_B  0                       /* 16384 B */
#define FKT0_B 16384
#define FVS0_B (16384 + 9216)
#define FKT1_B (16384 + 2*9216)
#define FVS1_B (16384 + 3*9216)
#define FTOT_B (16384 + 4*9216)        /* 53248 B */

__global__ __launch_bounds__(128) void flash_h(
    const __half* __restrict__ qkv, __half* __restrict__ out)
{
  extern __shared__ char fsm[];
  uint32_t* QF = (uint32_t*)(fsm + FQF_B);
  const uint32_t sbase = smem_u32(fsm);
  const uint32_t KtB[2] = { sbase + FKT0_B, sbase + FKT1_B };
  const uint32_t VsB[2] = { sbase + FVS0_B, sbase + FVS1_B };

  const int tid  = threadIdx.x;
  const int lane = tid & 31;
  const int w    = tid >> 5;
  const int bx   = (int)gridDim.x - 1 - (int)blockIdx.x;   // LPT: heavy first
  const int bh   = blockIdx.y;
  const int b    = bh >> 4;
  const int h    = bh & 15;
  const int q0   = bx * 128;

  const __half* qb = qkv + ((size_t)b * SEQ + q0) * QKVF + h * HDIM;
  const __half* kb = qkv + ((size_t)b * SEQ) * QKVF + EMBED + h * HDIM;
  const __half* vb = kb + EMBED;

  auto fillkv = [&](int buf, int k0) {
    #pragma unroll
    for (int i = 0; i < 4; i++) {
      int idx = tid + 128 * i;
      int row = idx >> 3, ch = idx & 7;
      uint32_t off = (uint32_t)(row * 144 + ch * 16);
      cp16(KtB[buf] + off, kb + (size_t)(k0 + row) * QKVF + ch * 8);
      cp16(VsB[buf] + off, vb + (size_t)(k0 + row) * QKVF + ch * 8);
    }
    cpcommit();
  };
  fillkv(0, 0);

  // ---- Q scatter into fp16 fragment layout (once), scaled by 1/8 ----
  {
    const __half2 sc = __floats2half2_rn(0.125f, 0.125f);
    for (int e = tid; e < 128 * 8; e += 128) {
      int r = e >> 3, c8 = (e & 7) << 3;
      uint4 qv = *(const uint4*)(qb + (size_t)r * QKVF + c8);
      uint32_t wds[4] = { qv.x, qv.y, qv.z, qv.w };
      int wq = r >> 5, m = (r >> 4) & 1, rr = r & 15;
      int frag = (wq * 2 + m) * 4 + (c8 >> 4);
      int rg = (rr >> 3) | (((c8 & 15) >> 3) << 1);
      #pragma unroll
      for (int j = 0; j < 4; j++) {
        __half2 hv = __hmul2(*(__half2*)&wds[j], sc);
        QF[frag * 128 + ((rr & 7) * 4 + j) * 4 + rg] = *(uint32_t*)&hv;
      }
    }
  }
  __syncthreads();   // QF complete before hoisted fragment loads

  // ---- Q a-frags: load ONCE (hoisted out of kv loop) ----
  uint4 qa[2][4];
  #pragma unroll
  for (int m = 0; m < 2; m++)
    #pragma unroll
    for (int ks = 0; ks < 4; ks++)
      qa[m][ks] = *(const uint4*)&QF[(((w * 2 + m) * 4 + ks) * 128) + lane * 4];

  const int r0 = lane >> 2;
  const int tq = lane & 3;
  const int qmin = q0 + w * 32;
  const int qmax = qmin + 31;
  const int qg[2] = { qmin + r0, qmin + 16 + r0 };

  const uint32_t kb_lane = (uint32_t)((lane & 7) * 144 + (lane >> 3) * 16);
  const int vm = lane >> 3;
  const uint32_t vb_lane = (uint32_t)(((vm & 1) * 8 + (lane & 7)) * 144 +
                                      (vm >> 1) * 16);

  float mrow[2][2], lrow[2][2];
  #pragma unroll
  for (int m = 0; m < 2; m++) {
    mrow[m][0] = mrow[m][1] = -1e30f;
    lrow[m][0] = lrow[m][1] = 0.0f;
  }
  float o[2][8][4];
  #pragma unroll
  for (int m = 0; m < 2; m++)
    #pragma unroll
    for (int nt = 0; nt < 8; nt++)
      #pragma unroll
      for (int j = 0; j < 4; j++) o[m][nt][j] = 0.0f;

  const int nkv = 2 * bx + 2;
  for (int kv = 0; kv < nkv; kv++) {
    const int k0 = kv * 64;
    const int buf = kv & 1;
    // wait for fill(kv); barrier also orders all warps past compute(kv-1)
    cpwait<0>();
    __syncthreads();
    // overwrite buf^1 (last read in compute(kv-1), ordered by the barrier)
    if (kv + 1 < nkv) fillkv(buf ^ 1, k0 + 64);

    if (k0 > qmax) continue;

    // ---- S = Q @ K^T ----
    float s[2][8][4];
    #pragma unroll
    for (int m = 0; m < 2; m++)
      #pragma unroll
      for (int nt = 0; nt < 8; nt++)
        s[m][nt][0] = s[m][nt][1] = s[m][nt][2] = s[m][nt][3] = 0.0f;

    #pragma unroll
    for (int nt = 0; nt < 8; nt++) {
      uint4 kr0, kr1;
      ldsm4(kr0, KtB[buf] + kb_lane + (uint32_t)(nt * 8 * 144));
      ldsm4(kr1, KtB[buf] + kb_lane + (uint32_t)(nt * 8 * 144 + 64));
      uint2 bk[4] = { make_uint2(kr0.x, kr0.y), make_uint2(kr0.z, kr0.w),
                      make_uint2(kr1.x, kr1.y), make_uint2(kr1.z, kr1.w) };
      #pragma unroll
      for (int ks = 0; ks < 4; ks++) {
        mma_f16(s[0][nt], qa[0][ks], bk[ks]);
        mma_f16(s[1][nt], qa[1][ks], bk[ks]);
      }
    }

    // ---- causal mask ----
    if (k0 + 63 > qmin) {
      #pragma unroll
      for (int m = 0; m < 2; m++) {
        #pragma unroll
        for (int nt = 0; nt < 8; nt++) {
          int c0 = k0 + 8 * nt + 2 * tq;
          int c1 = c0 + 1;
          if (c0 > qg[m])     s[m][nt][0] = -1e30f;
          if (c1 > qg[m])     s[m][nt][1] = -1e30f;
          if (c0 > qg[m] + 8) s[m][nt][2] = -1e30f;
          if (c1 > qg[m] + 8) s[m][nt][3] = -1e30f;
        }
      }
    }

    // ---- online softmax; P stays in registers (overwrites s) ----
    #pragma unroll
    for (int m = 0; m < 2; m++) {
      float mx0 = -1e30f, mx1 = -1e30f;
      #pragma unroll
      for (int nt = 0; nt < 8; nt++) {
        mx0 = fmaxf(mx0, fmaxf(s[m][nt][0], s[m][nt][1]));
        mx1 = fmaxf(mx1, fmaxf(s[m][nt][2], s[m][nt][3]));
      }
      mx0 = fmaxf(mx0, __shfl_xor_sync(0xffffffffu, mx0, 1));
      mx0 = fmaxf(mx0, __shfl_xor_sync(0xffffffffu, mx0, 2));
      mx1 = fmaxf(mx1, __shfl_xor_sync(0xffffffffu, mx1, 1));
      mx1 = fmaxf(mx1, __shfl_xor_sync(0xffffffffu, mx1, 2));

      float mn0 = fmaxf(mrow[m][0], mx0), mn1 = fmaxf(mrow[m][1], mx1);
      float a0 = __expf(mrow[m][0] - mn0), a1 = __expf(mrow[m][1] - mn1);
      mrow[m][0] = mn0; mrow[m][1] = mn1;

      float rs0 = 0.0f, rs1 = 0.0f;
      #pragma unroll
      for (int nt = 0; nt < 8; nt++) {
        s[m][nt][0] = __expf(s[m][nt][0] - mn0);
        s[m][nt][1] = __expf(s[m][nt][1] - mn0);
        s[m][nt][2] = __expf(s[m][nt][2] - mn1);
        s[m][nt][3] = __expf(s[m][nt][3] - mn1);
        rs0 += s[m][nt][0] + s[m][nt][1];
        rs1 += s[m][nt][2] + s[m][nt][3];
      }
      rs0 += __shfl_xor_sync(0xffffffffu, rs0, 1);
      rs0 += __shfl_xor_sync(0xffffffffu, rs0, 2);
      rs1 += __shfl_xor_sync(0xffffffffu, rs1, 1);
      rs1 += __shfl_xor_sync(0xffffffffu, rs1, 2);
      lrow[m][0] = lrow[m][0] * a0 + rs0;
      lrow[m][1] = lrow[m][1] * a1 + rs1;
      #pragma unroll
      for (int nt = 0; nt < 8; nt++) {
        o[m][nt][0] *= a0; o[m][nt][1] *= a0;
        o[m][nt][2] *= a1; o[m][nt][3] *= a1;
      }
    }

    // ---- O += P @ V : P a-frags built directly from S c-frags ----
    #pragma unroll
    for (int ks = 0; ks < 4; ks++) {
      uint4 pa0 = make_uint4(f2h2(s[0][2*ks][0],   s[0][2*ks][1]),
                             f2h2(s[0][2*ks][2],   s[0][2*ks][3]),
                             f2h2(s[0][2*ks+1][0], s[0][2*ks+1][1]),
                             f2h2(s[0][2*ks+1][2], s[0][2*ks+1][3]));
      uint4 pa1 = make_uint4(f2h2(s[1][2*ks][0],   s[1][2*ks][1]),
                             f2h2(s[1][2*ks][2],   s[1][2*ks][3]),
                             f2h2(s[1][2*ks+1][0], s[1][2*ks+1][1]),
                             f2h2(s[1][2*ks+1][2], s[1][2*ks+1][3]));
      #pragma unroll
      for (int j = 0; j < 4; j++) {
        uint4 vr;
        ldsm4t(vr, VsB[buf] + vb_lane + (uint32_t)(16 * ks * 144 + j * 32));
        uint2 bv0 = make_uint2(vr.x, vr.y);
        uint2 bv1 = make_uint2(vr.z, vr.w);
        mma_f16(o[0][2*j],     pa0, bv0);
        mma_f16(o[0][2*j + 1], pa0, bv1);
        mma_f16(o[1][2*j],     pa1, bv0);
        mma_f16(o[1][2*j + 1], pa1, bv1);
      }
    }
  }

  // ---- epilogue: normalize, write fp16 [B,T,C] ----
  #pragma unroll
  for (int m = 0; m < 2; m++) {
    float inv0 = 1.0f / lrow[m][0], inv1 = 1.0f / lrow[m][1];
    __half* orow0 = out + ((size_t)b * SEQ + q0 + w * 32 + m * 16 + r0) * EMBED + h * HDIM;
    __half* orow1 = orow0 + (size_t)8 * EMBED;
    #pragma unroll
    for (int nt = 0; nt < 8; nt++) {
      *(uint32_t*)(orow0 + 8 * nt + 2 * tq) =
          f2h2(o[m][nt][0] * inv0, o[m][nt][1] * inv0);
      *(uint32_t*)(orow1 + 8 * nt + 2 * tq) =
          f2h2(o[m][nt][2] * inv1, o[m][nt][3] * inv1);
    }
  }
}

// ---------------------------------------------------------------------------
extern "C" void kernel_launch(void* const* d_in, const int* in_sizes, int n_in,
                              void* d_out, int out_size)
{
  (void)in_sizes; (void)n_in; (void)out_size;
  const float* x     = (const float*)d_in[0];
  const float* qkv_w = (const float*)d_in[1];
  const float* qkv_b = (const float*)d_in[2];
  const float* out_w = (const float*)d_in[3];
  const float* out_b = (const float*)d_in[4];
  float* y = (float*)d_out;

  __half *hx, *hwq, *hwo, *hqkv, *hatt;
  cudaGetSymbolAddress((void**)&hx,   g_hx);
  cudaGetSymbolAddress((void**)&hwq,  g_hw_qkv);
  cudaGetSymbolAddress((void**)&hwo,  g_hw_out);
  cudaGetSymbolAddress((void**)&hqkv, g_hqkv);
  cudaGetSymbolAddress((void**)&hatt, g_hatt);

  cudaFuncSetAttribute(gemm_h<true>,
                       cudaFuncAttributeMaxDynamicSharedMemorySize, GSMEM_BYTES);
  cudaFuncSetAttribute(gemm_h<false>,
                       cudaFuncAttributeMaxDynamicSharedMemorySize, GSMEM_BYTES);
  cudaFuncSetAttribute(flash_h,
                       cudaFuncAttributeMaxDynamicSharedMemorySize, FTOT_B);

  // 0) fp32 -> fp16 conversions
  {
    int n4x = MTOT * EMBED / 4;
    f2h_kernel<<<(n4x + 255) / 256, 256>>>((const float4*)x, (uint2*)hx, n4x);
    int n4q = QKVF * EMBED / 4;
    f2h_kernel<<<(n4q + 255) / 256, 256>>>((const float4*)qkv_w, (uint2*)hwq, n4q);
    int n4o = EMBED * EMBED / 4;
    f2h_kernel<<<(n4o + 255) / 256, 256>>>((const float4*)out_w, (uint2*)hwo, n4o);
  }

  // 1) QKV projection (fp16 in, fp16 out)
  gemm_h<true><<<dim3(QKVF/128, MTOT/128), 128, GSMEM_BYTES>>>(
      hx, hwq, qkv_b, hqkv, MTOT, QKVF, EMBED);
  // 2) Causal flash attention (fp16, reg-resident P@V, LPT, 1 barrier/iter)
  flash_h<<<dim3(SEQ/128, BATCH*NHEAD), 128, FTOT_B>>>(hqkv, hatt);
  // 3) Output projection (fp16 in, fp32 out)
  gemm_h<false><<<dim3(EMBED/128, MTOT/128), 128, GSMEM_BYTES>>>(
      hatt, hwo, out_b, y, MTOT, EMBED, EMBED);
}